// round 1
// baseline (speedup 1.0000x reference)
#include <cuda_runtime.h>
#include <cstdint>

// ---------------------------------------------------------------------------
// Problem constants
// ---------------------------------------------------------------------------
#define DIM_    768
#define HEADS_  12
#define DH_     64
#define INNER_  768
#define B_      4
#define SEQ_    1024
#define EPS_    1e-5f

static constexpr int  TOK  = B_ * SEQ_;          // 4096
static constexpr long NN   = (long)SEQ_ * SEQ_;  // 1M
static constexpr int  QKVW = 3 * INNER_;         // 2304

// ---------------------------------------------------------------------------
// Scratch (device globals; no allocation allowed)
// ---------------------------------------------------------------------------
__device__ float g_qkv  [(size_t)TOK * QKVW];                 //  37.7 MB
__device__ float g_attnA[(size_t)B_ * HEADS_ * SEQ_ * SEQ_];  // 201 MB
__device__ float g_attnB[(size_t)B_ * HEADS_ * SEQ_ * SEQ_];  // 201 MB
__device__ float g_outh [(size_t)TOK * INNER_];               //  12.6 MB

// ---------------------------------------------------------------------------
// Generic register-blocked SGEMM.
//   C[m,n] = alpha * sum_k A[m,k] * B(k,n)  (+ bias[n])
//   TRB=false: B stored [K,N] row-major (B[k*ldb+n])
//   TRB=true : B stored [N,K] row-major (B[n*ldb+k])   (used for Q*K^T)
// Batched via blockIdx.z:  z -> (outer = z/innerDiv, inner = z%innerDiv)
//   matrix pointer += outer*Outer + inner*Inner
// All of M,N,K must be divisible by BM,BN,BK (true for every call site here).
// ---------------------------------------------------------------------------
template<int BM, int BN, int BK, int TM, int TN, bool TRB>
__global__ __launch_bounds__((BM/TM)*(BN/TN))
void sgemm_kernel(const float* __restrict__ A,
                  const float* __restrict__ B,
                  float*       __restrict__ C,
                  const float* __restrict__ bias,
                  int M, int N, int K,
                  int lda, int ldb, int ldc,
                  long aOuter, long aInner,
                  long bOuter, long bInner,
                  long cOuter, long cInner,
                  int innerDiv, float alpha)
{
    constexpr int NT = (BM/TM)*(BN/TN);
    const int tid = threadIdx.x;
    const int tx  = tid % (BN/TN);
    const int ty  = tid / (BN/TN);

    const int z  = blockIdx.z;
    const int zo = z / innerDiv;
    const int zi = z % innerDiv;
    A += zo*aOuter + zi*aInner;
    B += zo*bOuter + zi*bInner;
    C += zo*cOuter + zi*cInner;

    const int row0 = blockIdx.y * BM;
    const int col0 = blockIdx.x * BN;

    __shared__ float As[BK][BM];
    __shared__ float Bs[BK][BN + 4];

    float acc[TM][TN];
    #pragma unroll
    for (int i = 0; i < TM; i++)
        #pragma unroll
        for (int j = 0; j < TN; j++) acc[i][j] = 0.f;

    for (int k0 = 0; k0 < K; k0 += BK) {
        // --- load A tile (BM x BK) -> As[k][m]
        #pragma unroll
        for (int i = tid; i < BM*BK; i += NT) {
            int m  = i / BK;
            int kk = i % BK;
            As[kk][m] = A[(long)(row0 + m)*lda + (k0 + kk)];
        }
        // --- load B tile (BK x BN) -> Bs[k][n]
        if (!TRB) {
            #pragma unroll
            for (int i = tid; i < BK*BN; i += NT) {
                int kk = i / BN;
                int n  = i % BN;
                Bs[kk][n] = B[(long)(k0 + kk)*ldb + (col0 + n)];
            }
        } else {
            #pragma unroll
            for (int i = tid; i < BK*BN; i += NT) {
                int n  = i / BK;
                int kk = i % BK;
                Bs[kk][n] = B[(long)(col0 + n)*ldb + (k0 + kk)];
            }
        }
        __syncthreads();

        #pragma unroll
        for (int kk = 0; kk < BK; kk++) {
            float ra[TM], rb[TN];
            #pragma unroll
            for (int i = 0; i < TM; i++) ra[i] = As[kk][ty*TM + i];
            #pragma unroll
            for (int j = 0; j < TN; j++) rb[j] = Bs[kk][tx*TN + j];
            #pragma unroll
            for (int i = 0; i < TM; i++)
                #pragma unroll
                for (int j = 0; j < TN; j++)
                    acc[i][j] += ra[i] * rb[j];
        }
        __syncthreads();
    }

    #pragma unroll
    for (int i = 0; i < TM; i++) {
        const long r = (long)(row0 + ty*TM + i) * ldc;
        #pragma unroll
        for (int j = 0; j < TN; j++) {
            const int c = col0 + tx*TN + j;
            float v = alpha * acc[i][j];
            if (bias) v += bias[c];
            C[r + c] = v;
        }
    }
}

// ---------------------------------------------------------------------------
// Row softmax, rows of length 1024, 256 threads per row.
// ---------------------------------------------------------------------------
__global__ __launch_bounds__(256)
void softmax1024_kernel(float* __restrict__ data)
{
    const long row = blockIdx.x;
    float* p = data + row * 1024;
    const int t = threadIdx.x;

    float v[4];
    #pragma unroll
    for (int i = 0; i < 4; i++) v[i] = p[t + i*256];

    float m = fmaxf(fmaxf(v[0], v[1]), fmaxf(v[2], v[3]));
    __shared__ float redm[8];
    __shared__ float reds[8];
    #pragma unroll
    for (int o = 16; o > 0; o >>= 1)
        m = fmaxf(m, __shfl_xor_sync(0xffffffffu, m, o));
    if ((t & 31) == 0) redm[t >> 5] = m;
    __syncthreads();
    if (t < 32) {
        float x = (t < 8) ? redm[t] : -3.4e38f;
        #pragma unroll
        for (int o = 4; o > 0; o >>= 1)
            x = fmaxf(x, __shfl_xor_sync(0xffffffffu, x, o));
        if (t == 0) redm[0] = x;
    }
    __syncthreads();
    m = redm[0];

    float s = 0.f;
    #pragma unroll
    for (int i = 0; i < 4; i++) { v[i] = __expf(v[i] - m); s += v[i]; }
    #pragma unroll
    for (int o = 16; o > 0; o >>= 1)
        s += __shfl_xor_sync(0xffffffffu, s, o);
    if ((t & 31) == 0) reds[t >> 5] = s;
    __syncthreads();
    if (t < 32) {
        float x = (t < 8) ? reds[t] : 0.f;
        #pragma unroll
        for (int o = 4; o > 0; o >>= 1)
            x += __shfl_xor_sync(0xffffffffu, x, o);
        if (t == 0) reds[0] = x;
    }
    __syncthreads();
    const float inv = 1.f / reds[0];

    #pragma unroll
    for (int i = 0; i < 4; i++) p[t + i*256] = v[i] * inv;
}

// ---------------------------------------------------------------------------
// Cross-head remix (12x12) + LayerNorm over heads, per (b,i,j).
// attnA layout [b,h,i,j] -> attnB layout [b,k,i,j]
// grid: (SEQ/256, SEQ, B), block 256 (threads over j)
// ---------------------------------------------------------------------------
__global__ __launch_bounds__(256)
void remix_ln_kernel(const float* __restrict__ attnA,
                     float*       __restrict__ attnB,
                     const float* __restrict__ W,      // [12,12] row-major
                     const float* __restrict__ gamma,  // [12]
                     const float* __restrict__ beta)   // [12]
{
    __shared__ float sW[HEADS_*HEADS_];
    __shared__ float sG[HEADS_], sB[HEADS_];
    if (threadIdx.x < HEADS_*HEADS_) sW[threadIdx.x] = W[threadIdx.x];
    if (threadIdx.x < HEADS_) { sG[threadIdx.x] = gamma[threadIdx.x];
                                sB[threadIdx.x] = beta[threadIdx.x]; }
    __syncthreads();

    const int j = blockIdx.x * blockDim.x + threadIdx.x;
    const int i = blockIdx.y;
    const int b = blockIdx.z;

    const long base = (((long)b*HEADS_)*SEQ_ + i)*SEQ_ + j;

    float a[HEADS_];
    #pragma unroll
    for (int h = 0; h < HEADS_; h++) a[h] = attnA[base + (long)h*NN];

    float mixed[HEADS_];
    float mu = 0.f;
    #pragma unroll
    for (int k = 0; k < HEADS_; k++) {
        float s = 0.f;
        #pragma unroll
        for (int h = 0; h < HEADS_; h++) s += a[h] * sW[h*HEADS_ + k];
        mixed[k] = s;
        mu += s;
    }
    mu *= (1.f / HEADS_);
    float var = 0.f;
    #pragma unroll
    for (int k = 0; k < HEADS_; k++) {
        float d = mixed[k] - mu;
        var += d * d;
    }
    var *= (1.f / HEADS_);
    const float inv = rsqrtf(var + EPS_);

    #pragma unroll
    for (int k = 0; k < HEADS_; k++)
        attnB[base + (long)k*NN] = (mixed[k] - mu) * inv * sG[k] + sB[k];
}

// ---------------------------------------------------------------------------
// Host launcher
// ---------------------------------------------------------------------------
extern "C" void kernel_launch(void* const* d_in, const int* in_sizes, int n_in,
                              void* d_out, int out_size)
{
    const float* x       = (const float*)d_in[0];  // [4,1024,768]
    const float* w_qkv   = (const float*)d_in[1];  // [768,2304]
    const float* reattnW = (const float*)d_in[2];  // [12,12]
    const float* gamma   = (const float*)d_in[3];  // [12]
    const float* beta    = (const float*)d_in[4];  // [12]
    const float* w_out   = (const float*)d_in[5];  // [768,768]
    const float* b_out   = (const float*)d_in[6];  // [768]
    float* out = (float*)d_out;                    // [4,1024,768]

    float *qkv, *attnA, *attnB, *outh;
    cudaGetSymbolAddress((void**)&qkv,   g_qkv);
    cudaGetSymbolAddress((void**)&attnA, g_attnA);
    cudaGetSymbolAddress((void**)&attnB, g_attnB);
    cudaGetSymbolAddress((void**)&outh,  g_outh);

    const float scale = 0.125f; // 64^-0.5

    // 1) qkv = x @ w_qkv : [4096,768] x [768,2304]
    {
        dim3 grid(QKVW/128, TOK/128, 1);
        sgemm_kernel<128,128,8,8,8,false><<<grid, 256>>>(
            x, w_qkv, qkv, nullptr,
            TOK, QKVW, DIM_,
            DIM_, QKVW, QKVW,
            0,0, 0,0, 0,0, 1, 1.f);
    }

    // 2) dots = scale * Q K^T per (b,h)  -> attnA [b,h,i,j]
    {
        dim3 grid(SEQ_/128, SEQ_/128, B_*HEADS_);
        sgemm_kernel<128,128,8,8,8,true><<<grid, 256>>>(
            qkv,                 // Q base
            qkv + INNER_,        // K base
            attnA, nullptr,
            SEQ_, SEQ_, DH_,
            QKVW, QKVW, SEQ_,
            (long)SEQ_*QKVW, DH_,        // A: b-stride, h-stride
            (long)SEQ_*QKVW, DH_,        // B
            (long)HEADS_*NN,  NN,        // C
            HEADS_, scale);
    }

    // 3) softmax over j (rows of attnA)
    softmax1024_kernel<<<B_*HEADS_*SEQ_, 256>>>(attnA);

    // 4) cross-head remix + LayerNorm -> attnB
    {
        dim3 grid(SEQ_/256, SEQ_, B_);
        remix_ln_kernel<<<grid, 256>>>(attnA, attnB, reattnW, gamma, beta);
    }

    // 5) out_heads = attnB @ V per (b,h) -> [b,i,(h,d)] = [4096,768]
    {
        dim3 grid(DH_/64, SEQ_/128, B_*HEADS_);
        sgemm_kernel<128,64,8,8,4,false><<<grid, 256>>>(
            attnB,
            qkv + 2*INNER_,      // V base
            outh, nullptr,
            SEQ_, DH_, SEQ_,
            SEQ_, QKVW, INNER_,
            (long)HEADS_*NN, NN,          // A: b-stride, h-stride
            (long)SEQ_*QKVW, DH_,         // B
            (long)SEQ_*INNER_, DH_,       // C
            HEADS_, 1.f);
    }

    // 6) out = out_heads @ w_out + b_out : [4096,768] x [768,768]
    {
        dim3 grid(INNER_/128, TOK/128, 1);
        sgemm_kernel<128,128,8,8,8,false><<<grid, 256>>>(
            outh, w_out, out, b_out,
            TOK, DIM_, INNER_,
            INNER_, DIM_, DIM_,
            0,0, 0,0, 0,0, 1, 1.f);
    }
}

// round 2
// speedup vs baseline: 2.6387x; 2.6387x over previous
#include <cuda_runtime.h>
#include <cstdint>

#define DIM_    768
#define HEADS_  12
#define DH_     64
#define INNER_  768
#define B_      4
#define SEQ_    1024
#define EPS_    1e-5f

static constexpr int  TOK  = B_ * SEQ_;          // 4096
static constexpr long NN   = (long)SEQ_ * SEQ_;  // 1M
static constexpr int  QKVW = 3 * INNER_;         // 2304

// ---------------------------------------------------------------------------
// Scratch
// ---------------------------------------------------------------------------
__device__ float g_qkv  [(size_t)TOK * QKVW];                 //  37.7 MB
__device__ float g_attnA[(size_t)B_ * HEADS_ * SEQ_ * SEQ_];  // 201 MB
__device__ float g_attnB[(size_t)B_ * HEADS_ * SEQ_ * SEQ_];  // 201 MB
__device__ float g_outh [(size_t)TOK * INNER_];               //  12.6 MB

// ---------------------------------------------------------------------------
// tf32 helpers
// ---------------------------------------------------------------------------
__device__ __forceinline__ uint32_t f2tf32(float f) {
    uint32_t u;
    asm("cvt.rna.tf32.f32 %0, %1;" : "=r"(u) : "f"(f));
    return u;
}

__device__ __forceinline__ void mma_tf32(float (&d)[4],
                                         const uint32_t (&a)[4],
                                         const uint32_t (&b)[2]) {
    asm volatile(
        "mma.sync.aligned.m16n8k8.row.col.f32.tf32.tf32.f32 "
        "{%0,%1,%2,%3}, {%4,%5,%6,%7}, {%8,%9}, {%0,%1,%2,%3};\n"
        : "+f"(d[0]), "+f"(d[1]), "+f"(d[2]), "+f"(d[3])
        : "r"(a[0]), "r"(a[1]), "r"(a[2]), "r"(a[3]),
          "r"(b[0]), "r"(b[1]));
}

// ---------------------------------------------------------------------------
// tf32 tensor-core GEMM.
//   C[m,n] = alpha * sum_k A[m,k]*B(k,n) (+ bias[n])
//   TRB=false: B is [K,N] row-major.  TRB=true: B is [N,K] row-major.
// Batched over blockIdx.z (zo = z/innerDiv, zi = z%innerDiv).
// M%BM==0, N%BN==0, K%16==0 required (true at all call sites).
// ---------------------------------------------------------------------------
template<int BM, int BN, int WR, int WC, bool TRB>
__global__ __launch_bounds__(WR*WC*32)
void tgemm_kernel(const float* __restrict__ A,
                  const float* __restrict__ B,
                  float*       __restrict__ C,
                  const float* __restrict__ bias,
                  int K, int lda, int ldb, int ldc,
                  long aOuter, long aInner,
                  long bOuter, long bInner,
                  long cOuter, long cInner,
                  int innerDiv, float alpha)
{
    constexpr int BK  = 16;
    constexpr int NTH = WR*WC*32;
    constexpr int MT  = BM / (WR*16);   // m16 tiles per warp
    constexpr int NT  = BN / (WC*8);    // n8 tiles per warp

    __shared__ uint32_t As[BM][BK + 4];
    __shared__ uint32_t Bs[BK][BN + 8];

    const int tid  = threadIdx.x;
    const int wid  = tid >> 5;
    const int lane = tid & 31;
    const int wr   = wid / WC;
    const int wc   = wid % WC;
    const int g    = lane >> 2;
    const int tq   = lane & 3;

    const int z  = blockIdx.z;
    const int zo = z / innerDiv;
    const int zi = z % innerDiv;
    A += zo*aOuter + zi*aInner;
    B += zo*bOuter + zi*bInner;
    C += zo*cOuter + zi*cInner;

    const int row0 = blockIdx.y * BM;
    const int col0 = blockIdx.x * BN;
    const int mw = wr * (MT*16);
    const int nw = wc * (NT*8);

    float d[MT][NT][4];
    #pragma unroll
    for (int i = 0; i < MT; i++)
        #pragma unroll
        for (int j = 0; j < NT; j++)
            #pragma unroll
            for (int r = 0; r < 4; r++) d[i][j][r] = 0.f;

    for (int k0 = 0; k0 < K; k0 += BK) {
        // ---- A tile: BM x 16, row-major float4 loads
        #pragma unroll
        for (int it = tid; it < BM*BK/4; it += NTH) {
            const int row = it >> 2;            // BK/4 == 4
            const int c4  = (it & 3) * 4;
            const float4 fv = *reinterpret_cast<const float4*>(
                A + (long)(row0 + row)*lda + k0 + c4);
            As[row][c4+0] = f2tf32(fv.x);
            As[row][c4+1] = f2tf32(fv.y);
            As[row][c4+2] = f2tf32(fv.z);
            As[row][c4+3] = f2tf32(fv.w);
        }
        // ---- B tile: 16 x BN
        if (!TRB) {
            #pragma unroll
            for (int it = tid; it < BK*BN/4; it += NTH) {
                const int kr = it / (BN/4);
                const int c4 = (it % (BN/4)) * 4;
                const float4 fv = *reinterpret_cast<const float4*>(
                    B + (long)(k0 + kr)*ldb + col0 + c4);
                Bs[kr][c4+0] = f2tf32(fv.x);
                Bs[kr][c4+1] = f2tf32(fv.y);
                Bs[kr][c4+2] = f2tf32(fv.z);
                Bs[kr][c4+3] = f2tf32(fv.w);
            }
        } else {
            #pragma unroll
            for (int it = tid; it < BK*BN/4; it += NTH) {
                const int n  = it >> 2;         // BK/4 == 4
                const int c4 = (it & 3) * 4;
                const float4 fv = *reinterpret_cast<const float4*>(
                    B + (long)(col0 + n)*ldb + k0 + c4);
                Bs[c4+0][n] = f2tf32(fv.x);
                Bs[c4+1][n] = f2tf32(fv.y);
                Bs[c4+2][n] = f2tf32(fv.z);
                Bs[c4+3][n] = f2tf32(fv.w);
            }
        }
        __syncthreads();

        #pragma unroll
        for (int kk = 0; kk < 2; kk++) {
            const int kc = kk*8;
            uint32_t a[MT][4], b[NT][2];
            #pragma unroll
            for (int mt = 0; mt < MT; mt++) {
                const int r = mw + mt*16 + g;
                a[mt][0] = As[r    ][kc + tq    ];
                a[mt][1] = As[r + 8][kc + tq    ];
                a[mt][2] = As[r    ][kc + tq + 4];
                a[mt][3] = As[r + 8][kc + tq + 4];
            }
            #pragma unroll
            for (int nt = 0; nt < NT; nt++) {
                const int c = nw + nt*8 + g;
                b[nt][0] = Bs[kc + tq    ][c];
                b[nt][1] = Bs[kc + tq + 4][c];
            }
            #pragma unroll
            for (int mt = 0; mt < MT; mt++)
                #pragma unroll
                for (int nt = 0; nt < NT; nt++)
                    mma_tf32(d[mt][nt], a[mt], b[nt]);
        }
        __syncthreads();
    }

    // ---- epilogue
    #pragma unroll
    for (int mt = 0; mt < MT; mt++) {
        const int r0 = row0 + mw + mt*16 + g;
        #pragma unroll
        for (int nt = 0; nt < NT; nt++) {
            const int c = col0 + nw + nt*8 + tq*2;
            float bx = 0.f, by = 0.f;
            if (bias) { bx = bias[c]; by = bias[c+1]; }
            float2 v0 = { alpha*d[mt][nt][0] + bx, alpha*d[mt][nt][1] + by };
            float2 v1 = { alpha*d[mt][nt][2] + bx, alpha*d[mt][nt][3] + by };
            *reinterpret_cast<float2*>(&C[(long)r0*ldc + c])       = v0;
            *reinterpret_cast<float2*>(&C[(long)(r0+8)*ldc + c])   = v1;
        }
    }
}

// ---------------------------------------------------------------------------
// Fused softmax (over j) + cross-head remix (12x12) + LayerNorm (over heads).
// One block per (b,i); 256 threads over j (x4).
// Reads attnA [b,h,i,:] once; writes attnB [b,k,i,:] once.
// ---------------------------------------------------------------------------
__global__ __launch_bounds__(256)
void softmax_remix_ln_kernel(const float* __restrict__ attnA,
                             float*       __restrict__ attnB,
                             const float* __restrict__ W,
                             const float* __restrict__ gamma,
                             const float* __restrict__ beta)
{
    const int i = blockIdx.x;
    const int b = blockIdx.y;
    const int t = threadIdx.x;

    __shared__ float sW[HEADS_*HEADS_];
    __shared__ float sG[HEADS_], sBt[HEADS_];
    __shared__ float red[8];
    __shared__ float sInv[HEADS_];

    if (t < HEADS_*HEADS_) sW[t] = W[t];
    if (t < HEADS_) { sG[t] = gamma[t]; sBt[t] = beta[t]; }
    __syncthreads();

    const long rowbase = (long)b * HEADS_ * NN + (long)i * SEQ_;

    float v[HEADS_][4];
    #pragma unroll
    for (int h = 0; h < HEADS_; h++) {
        const float* p = attnA + rowbase + (long)h * NN;
        #pragma unroll
        for (int u = 0; u < 4; u++) v[h][u] = p[t + u*256];
    }

    // per-head softmax statistics; overwrite v with exp(v - max)
    for (int h = 0; h < HEADS_; h++) {
        float m = fmaxf(fmaxf(v[h][0], v[h][1]), fmaxf(v[h][2], v[h][3]));
        #pragma unroll
        for (int o = 16; o > 0; o >>= 1)
            m = fmaxf(m, __shfl_xor_sync(0xffffffffu, m, o));
        if ((t & 31) == 0) red[t >> 5] = m;
        __syncthreads();
        m = red[0];
        #pragma unroll
        for (int w = 1; w < 8; w++) m = fmaxf(m, red[w]);
        __syncthreads();

        float s = 0.f;
        #pragma unroll
        for (int u = 0; u < 4; u++) {
            v[h][u] = __expf(v[h][u] - m);
            s += v[h][u];
        }
        #pragma unroll
        for (int o = 16; o > 0; o >>= 1)
            s += __shfl_xor_sync(0xffffffffu, s, o);
        if ((t & 31) == 0) red[t >> 5] = s;
        __syncthreads();
        s = red[0];
        #pragma unroll
        for (int w = 1; w < 8; w++) s += red[w];
        if (t == 0) sInv[h] = 1.f / s;
        __syncthreads();
    }

    // remix + LN per column j
    #pragma unroll
    for (int u = 0; u < 4; u++) {
        float p[HEADS_];
        #pragma unroll
        for (int h = 0; h < HEADS_; h++) p[h] = v[h][u] * sInv[h];

        float mixed[HEADS_];
        float mu = 0.f;
        #pragma unroll
        for (int k = 0; k < HEADS_; k++) {
            float s = 0.f;
            #pragma unroll
            for (int h = 0; h < HEADS_; h++) s += p[h] * sW[h*HEADS_ + k];
            mixed[k] = s;
            mu += s;
        }
        mu *= (1.f / HEADS_);
        float var = 0.f;
        #pragma unroll
        for (int k = 0; k < HEADS_; k++) {
            const float dd = mixed[k] - mu;
            var += dd * dd;
        }
        var *= (1.f / HEADS_);
        const float inv = rsqrtf(var + EPS_);

        const int j = t + u*256;
        #pragma unroll
        for (int k = 0; k < HEADS_; k++)
            attnB[rowbase + (long)k*NN + j] =
                (mixed[k] - mu) * inv * sG[k] + sBt[k];
    }
}

// ---------------------------------------------------------------------------
// Host launcher
// ---------------------------------------------------------------------------
extern "C" void kernel_launch(void* const* d_in, const int* in_sizes, int n_in,
                              void* d_out, int out_size)
{
    const float* x       = (const float*)d_in[0];  // [4,1024,768]
    const float* w_qkv   = (const float*)d_in[1];  // [768,2304]
    const float* reattnW = (const float*)d_in[2];  // [12,12]
    const float* gamma   = (const float*)d_in[3];  // [12]
    const float* beta    = (const float*)d_in[4];  // [12]
    const float* w_out   = (const float*)d_in[5];  // [768,768]
    const float* b_out   = (const float*)d_in[6];  // [768]
    float* out = (float*)d_out;                    // [4,1024,768]

    float *qkv, *attnA, *attnB, *outh;
    cudaGetSymbolAddress((void**)&qkv,   g_qkv);
    cudaGetSymbolAddress((void**)&attnA, g_attnA);
    cudaGetSymbolAddress((void**)&attnB, g_attnB);
    cudaGetSymbolAddress((void**)&outh,  g_outh);

    const float scale = 0.125f; // 64^-0.5

    // 1) qkv = x @ w_qkv : [4096,768] x [768,2304]
    {
        dim3 grid(QKVW/128, TOK/128, 1);
        tgemm_kernel<128,128,2,4,false><<<grid, 256>>>(
            x, w_qkv, qkv, nullptr,
            DIM_, DIM_, QKVW, QKVW,
            0,0, 0,0, 0,0, 1, 1.f);
    }

    // 2) dots = scale * Q K^T per (b,h) -> attnA [b,h,i,j]
    {
        dim3 grid(SEQ_/128, SEQ_/128, B_*HEADS_);
        tgemm_kernel<128,128,2,4,true><<<grid, 256>>>(
            qkv, qkv + INNER_, attnA, nullptr,
            DH_, QKVW, QKVW, SEQ_,
            (long)SEQ_*QKVW, DH_,
            (long)SEQ_*QKVW, DH_,
            (long)HEADS_*NN,  NN,
            HEADS_, scale);
    }

    // 3) softmax + remix + LN -> attnB
    {
        dim3 grid(SEQ_, B_);
        softmax_remix_ln_kernel<<<grid, 256>>>(attnA, attnB, reattnW, gamma, beta);
    }

    // 4) out_heads = attnB @ V per (b,h) -> [4096,768]
    {
        dim3 grid(1, SEQ_/64, B_*HEADS_);
        tgemm_kernel<64,64,2,2,false><<<grid, 128>>>(
            attnB, qkv + 2*INNER_, outh, nullptr,
            SEQ_, SEQ_, QKVW, INNER_,
            (long)HEADS_*NN, NN,
            (long)SEQ_*QKVW, DH_,
            (long)SEQ_*INNER_, DH_,
            HEADS_, 1.f);
    }

    // 5) out = out_heads @ w_out + b_out : [4096,768] x [768,768]
    {
        dim3 grid(INNER_/128, TOK/128, 1);
        tgemm_kernel<128,128,2,4,false><<<grid, 256>>>(
            outh, w_out, out, b_out,
            INNER_, INNER_, DIM_, DIM_,
            0,0, 0,0, 0,0, 1, 1.f);
    }
}

// round 3
// speedup vs baseline: 3.1946x; 1.2107x over previous
#include <cuda_runtime.h>
#include <cstdint>

#define DIM_    768
#define HEADS_  12
#define DH_     64
#define INNER_  768
#define B_      4
#define SEQ_    1024
#define EPS_    1e-5f

static constexpr int  TOK  = B_ * SEQ_;          // 4096
static constexpr long NN   = (long)SEQ_ * SEQ_;  // 1M
static constexpr int  QKVW = 3 * INNER_;         // 2304

// ---------------------------------------------------------------------------
// Scratch
// ---------------------------------------------------------------------------
__device__ float g_qkv  [(size_t)TOK * QKVW];
__device__ float g_attnA[(size_t)B_ * HEADS_ * SEQ_ * SEQ_];
__device__ float g_attnB[(size_t)B_ * HEADS_ * SEQ_ * SEQ_];
__device__ float g_outh [(size_t)TOK * INNER_];

// ---------------------------------------------------------------------------
// helpers
// ---------------------------------------------------------------------------
__device__ __forceinline__ uint32_t f2tf32(float f) {
    uint32_t u;
    asm("cvt.rna.tf32.f32 %0, %1;" : "=r"(u) : "f"(f));
    return u;
}

__device__ __forceinline__ void mma_tf32(float (&d)[4],
                                         const uint32_t (&a)[4],
                                         const uint32_t (&b)[2]) {
    asm volatile(
        "mma.sync.aligned.m16n8k8.row.col.f32.tf32.tf32.f32 "
        "{%0,%1,%2,%3}, {%4,%5,%6,%7}, {%8,%9}, {%0,%1,%2,%3};\n"
        : "+f"(d[0]), "+f"(d[1]), "+f"(d[2]), "+f"(d[3])
        : "r"(a[0]), "r"(a[1]), "r"(a[2]), "r"(a[3]),
          "r"(b[0]), "r"(b[1]));
}

__device__ __forceinline__ void cpasync16(float* smem, const float* gmem) {
    uint32_t s = (uint32_t)__cvta_generic_to_shared(smem);
    asm volatile("cp.async.cg.shared.global [%0], [%1], 16;\n"
                 :: "r"(s), "l"(gmem));
}
#define CP_COMMIT() asm volatile("cp.async.commit_group;\n" ::: "memory")
#define CP_WAIT1()  asm volatile("cp.async.wait_group 1;\n" ::: "memory")

// ---------------------------------------------------------------------------
// tf32 tensor-core GEMM, cp.async double-buffered.
//   C[m,n] = alpha * sum_k A[m,k]*B(k,n) (+ bias[n])
//   TRB=false: B is [K,N] row-major.  TRB=true: B is [N,K] row-major.
// Batched over blockIdx.z (zo = z/innerDiv, zi = z%innerDiv).
// Requires M%BM==0, N%BN==0, K%16==0 (true at all call sites).
// smem holds raw fp32; tf32 conversion at fragment load.
// ---------------------------------------------------------------------------
template<int BM, int BN, int WR, int WC, bool TRB>
__global__ __launch_bounds__(WR*WC*32)
void tgemm_kernel(const float* __restrict__ A,
                  const float* __restrict__ B,
                  float*       __restrict__ C,
                  const float* __restrict__ bias,
                  int K, int lda, int ldb, int ldc,
                  long aOuter, long aInner,
                  long bOuter, long bInner,
                  long cOuter, long cInner,
                  int innerDiv, float alpha)
{
    constexpr int BK   = 16;
    constexpr int NTH  = WR*WC*32;
    constexpr int MT   = BM / (WR*16);
    constexpr int NT   = BN / (WC*8);
    constexpr int ALD  = BK + 4;
    constexpr int BLD  = TRB ? (BK + 4) : (BN + 8);
    constexpr int BROW = TRB ? BN : BK;

    __shared__ float As[2][BM*ALD];
    __shared__ float Bs[2][BROW*BLD];

    const int tid  = threadIdx.x;
    const int wid  = tid >> 5;
    const int lane = tid & 31;
    const int wr   = wid / WC;
    const int wc   = wid % WC;
    const int g    = lane >> 2;
    const int tq   = lane & 3;

    const int z  = blockIdx.z;
    const int zo = z / innerDiv;
    const int zi = z % innerDiv;
    A += zo*aOuter + zi*aInner;
    B += zo*bOuter + zi*bInner;
    C += zo*cOuter + zi*cInner;

    const int row0 = blockIdx.y * BM;
    const int col0 = blockIdx.x * BN;
    const int mw   = wr * (MT*16);
    const int nw   = wc * (NT*8);

    float d[MT][NT][4];
    #pragma unroll
    for (int i = 0; i < MT; i++)
        #pragma unroll
        for (int j = 0; j < NT; j++)
            #pragma unroll
            for (int r = 0; r < 4; r++) d[i][j][r] = 0.f;

    const int nk = K / BK;

    auto issue = [&](int kt, int s) {
        const int k0 = kt * BK;
        #pragma unroll
        for (int it = tid; it < BM*4; it += NTH) {
            const int row = it >> 2;
            const int c4  = (it & 3) * 4;
            cpasync16(&As[s][row*ALD + c4],
                      A + (long)(row0 + row)*lda + k0 + c4);
        }
        if (!TRB) {
            #pragma unroll
            for (int it = tid; it < 4*BN; it += NTH) {
                const int kr = it / (BN/4);
                const int c4 = (it % (BN/4)) * 4;
                cpasync16(&Bs[s][kr*BLD + c4],
                          B + (long)(k0 + kr)*ldb + col0 + c4);
            }
        } else {
            #pragma unroll
            for (int it = tid; it < BN*4; it += NTH) {
                const int n  = it >> 2;
                const int c4 = (it & 3) * 4;
                cpasync16(&Bs[s][n*BLD + c4],
                          B + (long)(col0 + n)*ldb + k0 + c4);
            }
        }
    };

    issue(0, 0);
    CP_COMMIT();

    for (int i = 0; i < nk; i++) {
        if (i + 1 < nk) issue(i + 1, (i + 1) & 1);
        CP_COMMIT();
        CP_WAIT1();
        __syncthreads();

        const float* Ab = As[i & 1];
        const float* Bb = Bs[i & 1];

        #pragma unroll
        for (int kk = 0; kk < 2; kk++) {
            const int kc = kk*8;
            uint32_t a[MT][4], b[NT][2];
            #pragma unroll
            for (int mt = 0; mt < MT; mt++) {
                const int r = mw + mt*16 + g;
                a[mt][0] = f2tf32(Ab[ r     *ALD + kc + tq    ]);
                a[mt][1] = f2tf32(Ab[(r + 8)*ALD + kc + tq    ]);
                a[mt][2] = f2tf32(Ab[ r     *ALD + kc + tq + 4]);
                a[mt][3] = f2tf32(Ab[(r + 8)*ALD + kc + tq + 4]);
            }
            #pragma unroll
            for (int nt = 0; nt < NT; nt++) {
                const int c = nw + nt*8 + g;
                if (!TRB) {
                    b[nt][0] = f2tf32(Bb[(kc + tq    )*BLD + c]);
                    b[nt][1] = f2tf32(Bb[(kc + tq + 4)*BLD + c]);
                } else {
                    b[nt][0] = f2tf32(Bb[c*BLD + kc + tq    ]);
                    b[nt][1] = f2tf32(Bb[c*BLD + kc + tq + 4]);
                }
            }
            #pragma unroll
            for (int mt = 0; mt < MT; mt++)
                #pragma unroll
                for (int nt = 0; nt < NT; nt++)
                    mma_tf32(d[mt][nt], a[mt], b[nt]);
        }
        __syncthreads();
    }

    #pragma unroll
    for (int mt = 0; mt < MT; mt++) {
        const int r0 = row0 + mw + mt*16 + g;
        #pragma unroll
        for (int nt = 0; nt < NT; nt++) {
            const int c = col0 + nw + nt*8 + tq*2;
            float bx = 0.f, by = 0.f;
            if (bias) { bx = bias[c]; by = bias[c+1]; }
            float2 v0 = { alpha*d[mt][nt][0] + bx, alpha*d[mt][nt][1] + by };
            float2 v1 = { alpha*d[mt][nt][2] + bx, alpha*d[mt][nt][3] + by };
            *reinterpret_cast<float2*>(&C[(long)r0*ldc + c])     = v0;
            *reinterpret_cast<float2*>(&C[(long)(r0+8)*ldc + c]) = v1;
        }
    }
}

// ---------------------------------------------------------------------------
// Fused softmax + cross-head remix + LayerNorm. One block per (b,i).
// ---------------------------------------------------------------------------
__global__ __launch_bounds__(256)
void softmax_remix_ln_kernel(const float* __restrict__ attnA,
                             float*       __restrict__ attnB,
                             const float* __restrict__ W,
                             const float* __restrict__ gamma,
                             const float* __restrict__ beta)
{
    const int i = blockIdx.x;
    const int b = blockIdx.y;
    const int t = threadIdx.x;

    __shared__ float sW[HEADS_*HEADS_];
    __shared__ float sG[HEADS_], sBt[HEADS_];
    __shared__ float red[8][HEADS_];

    if (t < HEADS_*HEADS_) sW[t] = W[t];
    if (t < HEADS_) { sG[t] = gamma[t]; sBt[t] = beta[t]; }

    const long rowbase = (long)b * HEADS_ * NN + (long)i * SEQ_;

    float4 v[HEADS_];
    #pragma unroll
    for (int h = 0; h < HEADS_; h++)
        v[h] = *reinterpret_cast<const float4*>(attnA + rowbase + (long)h*NN + t*4);

    #pragma unroll
    for (int h = 0; h < HEADS_; h++) {
        float m = fmaxf(fmaxf(v[h].x, v[h].y), fmaxf(v[h].z, v[h].w));
        #pragma unroll
        for (int o = 16; o > 0; o >>= 1)
            m = fmaxf(m, __shfl_xor_sync(0xffffffffu, m, o));
        if ((t & 31) == 0) red[t >> 5][h] = m;
    }
    __syncthreads();
    float gm[HEADS_];
    #pragma unroll
    for (int h = 0; h < HEADS_; h++) {
        float m = red[0][h];
        #pragma unroll
        for (int w = 1; w < 8; w++) m = fmaxf(m, red[w][h]);
        gm[h] = m;
    }
    __syncthreads();

    #pragma unroll
    for (int h = 0; h < HEADS_; h++) {
        v[h].x = __expf(v[h].x - gm[h]);
        v[h].y = __expf(v[h].y - gm[h]);
        v[h].z = __expf(v[h].z - gm[h]);
        v[h].w = __expf(v[h].w - gm[h]);
        float s = v[h].x + v[h].y + v[h].z + v[h].w;
        #pragma unroll
        for (int o = 16; o > 0; o >>= 1)
            s += __shfl_xor_sync(0xffffffffu, s, o);
        if ((t & 31) == 0) red[t >> 5][h] = s;
    }
    __syncthreads();
    float inv[HEADS_];
    #pragma unroll
    for (int h = 0; h < HEADS_; h++) {
        float s = red[0][h];
        #pragma unroll
        for (int w = 1; w < 8; w++) s += red[w][h];
        inv[h] = 1.f / s;
    }

    float4 outv[HEADS_];
    #pragma unroll
    for (int u = 0; u < 4; u++) {
        float p[HEADS_];
        #pragma unroll
        for (int h = 0; h < HEADS_; h++) {
            float pv = (u == 0) ? v[h].x : (u == 1) ? v[h].y
                     : (u == 2) ? v[h].z : v[h].w;
            p[h] = pv * inv[h];
        }
        float mixed[HEADS_];
        float mu = 0.f;
        #pragma unroll
        for (int k = 0; k < HEADS_; k++) {
            float s = 0.f;
            #pragma unroll
            for (int h = 0; h < HEADS_; h++) s += p[h] * sW[h*HEADS_ + k];
            mixed[k] = s;
            mu += s;
        }
        mu *= (1.f / HEADS_);
        float var = 0.f;
        #pragma unroll
        for (int k = 0; k < HEADS_; k++) {
            const float dd = mixed[k] - mu;
            var += dd * dd;
        }
        var *= (1.f / HEADS_);
        const float ninv = rsqrtf(var + EPS_);

        #pragma unroll
        for (int k = 0; k < HEADS_; k++) {
            float r = (mixed[k] - mu) * ninv * sG[k] + sBt[k];
            if      (u == 0) outv[k].x = r;
            else if (u == 1) outv[k].y = r;
            else if (u == 2) outv[k].z = r;
            else             outv[k].w = r;
        }
    }
    #pragma unroll
    for (int k = 0; k < HEADS_; k++)
        *reinterpret_cast<float4*>(attnB + rowbase + (long)k*NN + t*4) = outv[k];
}

// ---------------------------------------------------------------------------
// Host launcher
// ---------------------------------------------------------------------------
extern "C" void kernel_launch(void* const* d_in, const int* in_sizes, int n_in,
                              void* d_out, int out_size)
{
    const float* x       = (const float*)d_in[0];
    const float* w_qkv   = (const float*)d_in[1];
    const float* reattnW = (const float*)d_in[2];
    const float* gamma   = (const float*)d_in[3];
    const float* beta    = (const float*)d_in[4];
    const float* w_out   = (const float*)d_in[5];
    const float* b_out   = (const float*)d_in[6];
    float* out = (float*)d_out;

    float *qkv, *attnA, *attnB, *outh;
    cudaGetSymbolAddress((void**)&qkv,   g_qkv);
    cudaGetSymbolAddress((void**)&attnA, g_attnA);
    cudaGetSymbolAddress((void**)&attnB, g_attnB);
    cudaGetSymbolAddress((void**)&outh,  g_outh);

    const float scale = 0.125f;

    // 1) qkv = x @ w_qkv : [4096,768] x [768,2304]
    {
        dim3 grid(QKVW/128, TOK/128, 1);
        tgemm_kernel<128,128,2,4,false><<<grid, 256>>>(
            x, w_qkv, qkv, nullptr,
            DIM_, DIM_, QKVW, QKVW,
            0,0, 0,0, 0,0, 1, 1.f);
    }

    // 2) dots = scale * Q K^T per (b,h) -> attnA [b,h,i,j]
    {
        dim3 grid(SEQ_/128, SEQ_/128, B_*HEADS_);
        tgemm_kernel<128,128,2,4,true><<<grid, 256>>>(
            qkv, qkv + INNER_, attnA, nullptr,
            DH_, QKVW, QKVW, SEQ_,
            (long)SEQ_*QKVW, DH_,
            (long)SEQ_*QKVW, DH_,
            (long)HEADS_*NN,  NN,
            HEADS_, scale);
    }

    // 3) softmax + remix + LN -> attnB
    {
        dim3 grid(SEQ_, B_);
        softmax_remix_ln_kernel<<<grid, 256>>>(attnA, attnB, reattnW, gamma, beta);
    }

    // 4) out_heads = attnB @ V per (b,h) -> [4096,768]
    {
        dim3 grid(1, SEQ_/128, B_*HEADS_);
        tgemm_kernel<128,64,2,4,false><<<grid, 256>>>(
            attnB, qkv + 2*INNER_, outh, nullptr,
            SEQ_, SEQ_, QKVW, INNER_,
            (long)HEADS_*NN, NN,
            (long)SEQ_*QKVW, DH_,
            (long)SEQ_*INNER_, DH_,
            HEADS_, 1.f);
    }

    // 5) out = out_heads @ w_out + b_out : [4096,768] x [768,768]
    {
        dim3 grid(INNER_/128, TOK/128, 1);
        tgemm_kernel<128,128,2,4,false><<<grid, 256>>>(
            outh, w_out, out, b_out,
            INNER_, INNER_, DIM_, DIM_,
            0,0, 0,0, 0,0, 1, 1.f);
    }
}

// round 4
// speedup vs baseline: 3.1948x; 1.0001x over previous
#include <cuda_runtime.h>
#include <cstdint>

#define DIM_    768
#define HEADS_  12
#define DH_     64
#define INNER_  768
#define B_      4
#define SEQ_    1024
#define EPS_    1e-5f

static constexpr int  TOK  = B_ * SEQ_;          // 4096
static constexpr long NN   = (long)SEQ_ * SEQ_;  // 1M
static constexpr int  QKVW = 3 * INNER_;         // 2304

// ---------------------------------------------------------------------------
// Scratch
// ---------------------------------------------------------------------------
__device__ float g_qkv  [(size_t)TOK * QKVW];
__device__ float g_attnA[(size_t)B_ * HEADS_ * SEQ_ * SEQ_];
__device__ float g_attnB[(size_t)B_ * HEADS_ * SEQ_ * SEQ_];
__device__ float g_outh [(size_t)TOK * INNER_];

// ---------------------------------------------------------------------------
// helpers
// ---------------------------------------------------------------------------
__device__ __forceinline__ uint32_t f2tf32(float f) {
    uint32_t u;
    asm("cvt.rna.tf32.f32 %0, %1;" : "=r"(u) : "f"(f));
    return u;
}

__device__ __forceinline__ void mma_tf32(float (&d)[4],
                                         const uint32_t (&a)[4],
                                         const uint32_t (&b)[2]) {
    asm volatile(
        "mma.sync.aligned.m16n8k8.row.col.f32.tf32.tf32.f32 "
        "{%0,%1,%2,%3}, {%4,%5,%6,%7}, {%8,%9}, {%0,%1,%2,%3};\n"
        : "+f"(d[0]), "+f"(d[1]), "+f"(d[2]), "+f"(d[3])
        : "r"(a[0]), "r"(a[1]), "r"(a[2]), "r"(a[3]),
          "r"(b[0]), "r"(b[1]));
}

__device__ __forceinline__ void cpasync16(float* smem, const float* gmem) {
    uint32_t s = (uint32_t)__cvta_generic_to_shared(smem);
    asm volatile("cp.async.cg.shared.global [%0], [%1], 16;\n"
                 :: "r"(s), "l"(gmem));
}
#define CP_COMMIT() asm volatile("cp.async.commit_group;\n" ::: "memory")
#define CP_WAIT1()  asm volatile("cp.async.wait_group 1;\n" ::: "memory")

// ---------------------------------------------------------------------------
// tf32 tensor-core GEMM, cp.async double-buffered.
//   C[m,n] = alpha * sum_k A[m,k]*B(k,n) (+ bias[n])
//   TRB=false: B is [K,N] row-major.  TRB=true: B is [N,K] row-major.
// Batched over blockIdx.z (zo = z/innerDiv, zi = z%innerDiv).
// Requires M%BM==0, N%BN==0, K%16==0 (true at all call sites).
// smem holds raw fp32; tf32 conversion at fragment load.
// ---------------------------------------------------------------------------
template<int BM, int BN, int WR, int WC, bool TRB>
__global__ __launch_bounds__(WR*WC*32)
void tgemm_kernel(const float* __restrict__ A,
                  const float* __restrict__ B,
                  float*       __restrict__ C,
                  const float* __restrict__ bias,
                  int K, int lda, int ldb, int ldc,
                  long aOuter, long aInner,
                  long bOuter, long bInner,
                  long cOuter, long cInner,
                  int innerDiv, float alpha)
{
    constexpr int BK   = 16;
    constexpr int NTH  = WR*WC*32;
    constexpr int MT   = BM / (WR*16);
    constexpr int NT   = BN / (WC*8);
    constexpr int ALD  = BK + 4;
    constexpr int BLD  = TRB ? (BK + 4) : (BN + 8);
    constexpr int BROW = TRB ? BN : BK;

    __shared__ float As[2][BM*ALD];
    __shared__ float Bs[2][BROW*BLD];

    const int tid  = threadIdx.x;
    const int wid  = tid >> 5;
    const int lane = tid & 31;
    const int wr   = wid / WC;
    const int wc   = wid % WC;
    const int g    = lane >> 2;
    const int tq   = lane & 3;

    const int z  = blockIdx.z;
    const int zo = z / innerDiv;
    const int zi = z % innerDiv;
    A += zo*aOuter + zi*aInner;
    B += zo*bOuter + zi*bInner;
    C += zo*cOuter + zi*cInner;

    const int row0 = blockIdx.y * BM;
    const int col0 = blockIdx.x * BN;
    const int mw   = wr * (MT*16);
    const int nw   = wc * (NT*8);

    float d[MT][NT][4];
    #pragma unroll
    for (int i = 0; i < MT; i++)
        #pragma unroll
        for (int j = 0; j < NT; j++)
            #pragma unroll
            for (int r = 0; r < 4; r++) d[i][j][r] = 0.f;

    const int nk = K / BK;

    auto issue = [&](int kt, int s) {
        const int k0 = kt * BK;
        #pragma unroll
        for (int it = tid; it < BM*4; it += NTH) {
            const int row = it >> 2;
            const int c4  = (it & 3) * 4;
            cpasync16(&As[s][row*ALD + c4],
                      A + (long)(row0 + row)*lda + k0 + c4);
        }
        if (!TRB) {
            #pragma unroll
            for (int it = tid; it < 4*BN; it += NTH) {
                const int kr = it / (BN/4);
                const int c4 = (it % (BN/4)) * 4;
                cpasync16(&Bs[s][kr*BLD + c4],
                          B + (long)(k0 + kr)*ldb + col0 + c4);
            }
        } else {
            #pragma unroll
            for (int it = tid; it < BN*4; it += NTH) {
                const int n  = it >> 2;
                const int c4 = (it & 3) * 4;
                cpasync16(&Bs[s][n*BLD + c4],
                          B + (long)(col0 + n)*ldb + k0 + c4);
            }
        }
    };

    issue(0, 0);
    CP_COMMIT();

    for (int i = 0; i < nk; i++) {
        if (i + 1 < nk) issue(i + 1, (i + 1) & 1);
        CP_COMMIT();
        CP_WAIT1();
        __syncthreads();

        const float* Ab = As[i & 1];
        const float* Bb = Bs[i & 1];

        #pragma unroll
        for (int kk = 0; kk < 2; kk++) {
            const int kc = kk*8;
            uint32_t a[MT][4], b[NT][2];
            #pragma unroll
            for (int mt = 0; mt < MT; mt++) {
                const int r = mw + mt*16 + g;
                a[mt][0] = f2tf32(Ab[ r     *ALD + kc + tq    ]);
                a[mt][1] = f2tf32(Ab[(r + 8)*ALD + kc + tq    ]);
                a[mt][2] = f2tf32(Ab[ r     *ALD + kc + tq + 4]);
                a[mt][3] = f2tf32(Ab[(r + 8)*ALD + kc + tq + 4]);
            }
            #pragma unroll
            for (int nt = 0; nt < NT; nt++) {
                const int c = nw + nt*8 + g;
                if (!TRB) {
                    b[nt][0] = f2tf32(Bb[(kc + tq    )*BLD + c]);
                    b[nt][1] = f2tf32(Bb[(kc + tq + 4)*BLD + c]);
                } else {
                    b[nt][0] = f2tf32(Bb[c*BLD + kc + tq    ]);
                    b[nt][1] = f2tf32(Bb[c*BLD + kc + tq + 4]);
                }
            }
            #pragma unroll
            for (int mt = 0; mt < MT; mt++)
                #pragma unroll
                for (int nt = 0; nt < NT; nt++)
                    mma_tf32(d[mt][nt], a[mt], b[nt]);
        }
        __syncthreads();
    }

    #pragma unroll
    for (int mt = 0; mt < MT; mt++) {
        const int r0 = row0 + mw + mt*16 + g;
        #pragma unroll
        for (int nt = 0; nt < NT; nt++) {
            const int c = col0 + nw + nt*8 + tq*2;
            float bx = 0.f, by = 0.f;
            if (bias) { bx = bias[c]; by = bias[c+1]; }
            float2 v0 = { alpha*d[mt][nt][0] + bx, alpha*d[mt][nt][1] + by };
            float2 v1 = { alpha*d[mt][nt][2] + bx, alpha*d[mt][nt][3] + by };
            *reinterpret_cast<float2*>(&C[(long)r0*ldc + c])     = v0;
            *reinterpret_cast<float2*>(&C[(long)(r0+8)*ldc + c]) = v1;
        }
    }
}

// ---------------------------------------------------------------------------
// Fused softmax + cross-head remix + LayerNorm. One block per (b,i).
// ---------------------------------------------------------------------------
__global__ __launch_bounds__(256)
void softmax_remix_ln_kernel(const float* __restrict__ attnA,
                             float*       __restrict__ attnB,
                             const float* __restrict__ W,
                             const float* __restrict__ gamma,
                             const float* __restrict__ beta)
{
    const int i = blockIdx.x;
    const int b = blockIdx.y;
    const int t = threadIdx.x;

    __shared__ float sW[HEADS_*HEADS_];
    __shared__ float sG[HEADS_], sBt[HEADS_];
    __shared__ float red[8][HEADS_];

    if (t < HEADS_*HEADS_) sW[t] = W[t];
    if (t < HEADS_) { sG[t] = gamma[t]; sBt[t] = beta[t]; }

    const long rowbase = (long)b * HEADS_ * NN + (long)i * SEQ_;

    float4 v[HEADS_];
    #pragma unroll
    for (int h = 0; h < HEADS_; h++)
        v[h] = *reinterpret_cast<const float4*>(attnA + rowbase + (long)h*NN + t*4);

    #pragma unroll
    for (int h = 0; h < HEADS_; h++) {
        float m = fmaxf(fmaxf(v[h].x, v[h].y), fmaxf(v[h].z, v[h].w));
        #pragma unroll
        for (int o = 16; o > 0; o >>= 1)
            m = fmaxf(m, __shfl_xor_sync(0xffffffffu, m, o));
        if ((t & 31) == 0) red[t >> 5][h] = m;
    }
    __syncthreads();
    float gm[HEADS_];
    #pragma unroll
    for (int h = 0; h < HEADS_; h++) {
        float m = red[0][h];
        #pragma unroll
        for (int w = 1; w < 8; w++) m = fmaxf(m, red[w][h]);
        gm[h] = m;
    }
    __syncthreads();

    #pragma unroll
    for (int h = 0; h < HEADS_; h++) {
        v[h].x = __expf(v[h].x - gm[h]);
        v[h].y = __expf(v[h].y - gm[h]);
        v[h].z = __expf(v[h].z - gm[h]);
        v[h].w = __expf(v[h].w - gm[h]);
        float s = v[h].x + v[h].y + v[h].z + v[h].w;
        #pragma unroll
        for (int o = 16; o > 0; o >>= 1)
            s += __shfl_xor_sync(0xffffffffu, s, o);
        if ((t & 31) == 0) red[t >> 5][h] = s;
    }
    __syncthreads();
    float inv[HEADS_];
    #pragma unroll
    for (int h = 0; h < HEADS_; h++) {
        float s = red[0][h];
        #pragma unroll
        for (int w = 1; w < 8; w++) s += red[w][h];
        inv[h] = 1.f / s;
    }

    float4 outv[HEADS_];
    #pragma unroll
    for (int u = 0; u < 4; u++) {
        float p[HEADS_];
        #pragma unroll
        for (int h = 0; h < HEADS_; h++) {
            float pv = (u == 0) ? v[h].x : (u == 1) ? v[h].y
                     : (u == 2) ? v[h].z : v[h].w;
            p[h] = pv * inv[h];
        }
        float mixed[HEADS_];
        float mu = 0.f;
        #pragma unroll
        for (int k = 0; k < HEADS_; k++) {
            float s = 0.f;
            #pragma unroll
            for (int h = 0; h < HEADS_; h++) s += p[h] * sW[h*HEADS_ + k];
            mixed[k] = s;
            mu += s;
        }
        mu *= (1.f / HEADS_);
        float var = 0.f;
        #pragma unroll
        for (int k = 0; k < HEADS_; k++) {
            const float dd = mixed[k] - mu;
            var += dd * dd;
        }
        var *= (1.f / HEADS_);
        const float ninv = rsqrtf(var + EPS_);

        #pragma unroll
        for (int k = 0; k < HEADS_; k++) {
            float r = (mixed[k] - mu) * ninv * sG[k] + sBt[k];
            if      (u == 0) outv[k].x = r;
            else if (u == 1) outv[k].y = r;
            else if (u == 2) outv[k].z = r;
            else             outv[k].w = r;
        }
    }
    #pragma unroll
    for (int k = 0; k < HEADS_; k++)
        *reinterpret_cast<float4*>(attnB + rowbase + (long)k*NN + t*4) = outv[k];
}

// ---------------------------------------------------------------------------
// Host launcher
// ---------------------------------------------------------------------------
extern "C" void kernel_launch(void* const* d_in, const int* in_sizes, int n_in,
                              void* d_out, int out_size)
{
    const float* x       = (const float*)d_in[0];
    const float* w_qkv   = (const float*)d_in[1];
    const float* reattnW = (const float*)d_in[2];
    const float* gamma   = (const float*)d_in[3];
    const float* beta    = (const float*)d_in[4];
    const float* w_out   = (const float*)d_in[5];
    const float* b_out   = (const float*)d_in[6];
    float* out = (float*)d_out;

    float *qkv, *attnA, *attnB, *outh;
    cudaGetSymbolAddress((void**)&qkv,   g_qkv);
    cudaGetSymbolAddress((void**)&attnA, g_attnA);
    cudaGetSymbolAddress((void**)&attnB, g_attnB);
    cudaGetSymbolAddress((void**)&outh,  g_outh);

    const float scale = 0.125f;

    // 1) qkv = x @ w_qkv : [4096,768] x [768,2304]
    {
        dim3 grid(QKVW/128, TOK/128, 1);
        tgemm_kernel<128,128,2,4,false><<<grid, 256>>>(
            x, w_qkv, qkv, nullptr,
            DIM_, DIM_, QKVW, QKVW,
            0,0, 0,0, 0,0, 1, 1.f);
    }

    // 2) dots = scale * Q K^T per (b,h) -> attnA [b,h,i,j]
    {
        dim3 grid(SEQ_/128, SEQ_/128, B_*HEADS_);
        tgemm_kernel<128,128,2,4,true><<<grid, 256>>>(
            qkv, qkv + INNER_, attnA, nullptr,
            DH_, QKVW, QKVW, SEQ_,
            (long)SEQ_*QKVW, DH_,
            (long)SEQ_*QKVW, DH_,
            (long)HEADS_*NN,  NN,
            HEADS_, scale);
    }

    // 3) softmax + remix + LN -> attnB
    {
        dim3 grid(SEQ_, B_);
        softmax_remix_ln_kernel<<<grid, 256>>>(attnA, attnB, reattnW, gamma, beta);
    }

    // 4) out_heads = attnB @ V per (b,h) -> [4096,768]
    {
        dim3 grid(1, SEQ_/128, B_*HEADS_);
        tgemm_kernel<128,64,2,4,false><<<grid, 256>>>(
            attnB, qkv + 2*INNER_, outh, nullptr,
            SEQ_, SEQ_, QKVW, INNER_,
            (long)HEADS_*NN, NN,
            (long)SEQ_*QKVW, DH_,
            (long)SEQ_*INNER_, DH_,
            HEADS_, 1.f);
    }

    // 5) out = out_heads @ w_out + b_out : [4096,768] x [768,768]
    {
        dim3 grid(INNER_/128, TOK/128, 1);
        tgemm_kernel<128,128,2,4,false><<<grid, 256>>>(
            outh, w_out, out, b_out,
            INNER_, INNER_, DIM_, DIM_,
            0,0, 0,0, 0,0, 1, 1.f);
    }
}

// round 5
// speedup vs baseline: 3.3014x; 1.0334x over previous
#include <cuda_runtime.h>
#include <cstdint>

#define DIM_    768
#define HEADS_  12
#define DH_     64
#define INNER_  768
#define B_      4
#define SEQ_    1024
#define EPS_    1e-5f

static constexpr int  TOK  = B_ * SEQ_;          // 4096
static constexpr long NN   = (long)SEQ_ * SEQ_;  // 1M
static constexpr int  QKVW = 3 * INNER_;         // 2304

// ---------------------------------------------------------------------------
// Scratch
// ---------------------------------------------------------------------------
__device__ float g_qkv  [(size_t)TOK * QKVW];
__device__ float g_attnA[(size_t)B_ * HEADS_ * SEQ_ * SEQ_];
__device__ float g_attnB[(size_t)B_ * HEADS_ * SEQ_ * SEQ_];
__device__ float g_outh [(size_t)TOK * INNER_];

// ---------------------------------------------------------------------------
// helpers
// ---------------------------------------------------------------------------
__device__ __forceinline__ uint32_t f2tf32(float f) {
    uint32_t u;
    asm("cvt.rna.tf32.f32 %0, %1;" : "=r"(u) : "f"(f));
    return u;
}
__device__ __forceinline__ float roundtf(float f) {
    return __uint_as_float(f2tf32(f));
}

__device__ __forceinline__ void mma_tf32(float (&d)[4],
                                         const uint32_t (&a)[4],
                                         const uint32_t (&b)[2]) {
    asm volatile(
        "mma.sync.aligned.m16n8k8.row.col.f32.tf32.tf32.f32 "
        "{%0,%1,%2,%3}, {%4,%5,%6,%7}, {%8,%9}, {%0,%1,%2,%3};\n"
        : "+f"(d[0]), "+f"(d[1]), "+f"(d[2]), "+f"(d[3])
        : "r"(a[0]), "r"(a[1]), "r"(a[2]), "r"(a[3]),
          "r"(b[0]), "r"(b[1]));
}

__device__ __forceinline__ void cpasync16(float* smem, const float* gmem) {
    uint32_t s = (uint32_t)__cvta_generic_to_shared(smem);
    asm volatile("cp.async.cg.shared.global [%0], [%1], 16;\n"
                 :: "r"(s), "l"(gmem));
}
#define CP_COMMIT() asm volatile("cp.async.commit_group;\n" ::: "memory")
#define CP_WAIT1()  asm volatile("cp.async.wait_group 1;\n" ::: "memory")

// ---------------------------------------------------------------------------
// tf32 tensor-core GEMM, cp.async 3-stage pipeline, 1 sync/iter.
//   C[m,n] = alpha * sum_k A[m,k]*B(k,n) (+ bias[n])
//   TRB=false: B is [K,N] row-major.  TRB=true: B is [N,K] row-major.
//   CVTA/CVTB: convert that operand to tf32 at fragment load
//              (false => operand already tf32-rounded in gmem).
//   ROUND: round C to tf32 before store (for tf32 consumers downstream).
// Requires M%BM==0, N%BN==0, K%16==0, NTH==256.
// ---------------------------------------------------------------------------
template<int BM, int BN, int WR, int WC, bool TRB, bool CVTA, bool CVTB, bool ROUND>
__global__ __launch_bounds__(256)
void tgemm_kernel(const float* __restrict__ A,
                  const float* __restrict__ B,
                  float*       __restrict__ C,
                  const float* __restrict__ bias,
                  int K, int lda, int ldb, int ldc,
                  long aOuter, long aInner,
                  long bOuter, long bInner,
                  long cOuter, long cInner,
                  int innerDiv, float alpha)
{
    constexpr int BK   = 16;
    constexpr int NTH  = 256;
    constexpr int MT   = BM / (WR*16);
    constexpr int NT   = BN / (WC*8);
    constexpr int ALD  = BK + 4;
    constexpr int BLD  = TRB ? (BK + 4) : (BN + 8);
    constexpr int BROW = TRB ? BN : BK;
    constexpr int ASZ  = BM * ALD;
    constexpr int BSZ  = BROW * BLD;
    constexpr int AITER = BM * 4 / NTH;            // float4 loads per thread (A)
    constexpr int BITER = (TRB ? BN*4 : BK*BN/4) / NTH;

    extern __shared__ float dynsmem[];
    float* AsAll = dynsmem;            // 3 * ASZ
    float* BsAll = dynsmem + 3*ASZ;    // 3 * BSZ

    const int tid  = threadIdx.x;
    const int wid  = tid >> 5;
    const int lane = tid & 31;
    const int wr   = wid / WC;
    const int wc   = wid % WC;
    const int g    = lane >> 2;
    const int tq   = lane & 3;

    const int z  = blockIdx.z;
    const int zo = z / innerDiv;
    const int zi = z % innerDiv;
    A += zo*aOuter + zi*aInner;
    B += zo*bOuter + zi*bInner;
    C += zo*cOuter + zi*cInner;

    const int row0 = blockIdx.y * BM;
    const int col0 = blockIdx.x * BN;
    const int mw   = wr * (MT*16);
    const int nw   = wc * (NT*8);

    // ---- hoisted load addressing ---------------------------------------
    const int aRow = tid >> 2;
    const int aC4  = (tid & 3) * 4;
    const float* aBase = A + (long)(row0 + aRow)*lda + aC4;
    const int aSm0 = aRow*ALD + aC4;

    int bSm0;
    const float* bBase;
    if (!TRB) {
        const int bKr = tid / (BN/4);
        const int bC4 = (tid % (BN/4)) * 4;
        bBase = B + (long)bKr*ldb + col0 + bC4;
        bSm0  = bKr*BLD + bC4;
    } else {
        const int bN  = tid >> 2;
        const int bC4 = (tid & 3) * 4;
        bBase = B + (long)(col0 + bN)*ldb + bC4;
        bSm0  = bN*BLD + bC4;
    }
    constexpr int A_RSTEP = NTH >> 2;                      // rows per iter
    constexpr int B_RSTEP = TRB ? (NTH >> 2) : (NTH/(BN/4)); // rows per iter

    auto issue = [&](int kt, int s) {
        const int k0 = kt * BK;
        float* AsS = AsAll + s*ASZ;
        float* BsS = BsAll + s*BSZ;
        #pragma unroll
        for (int r = 0; r < AITER; r++)
            cpasync16(&AsS[aSm0 + r*A_RSTEP*ALD],
                      aBase + (long)r*A_RSTEP*lda + k0);
        if (!TRB) {
            #pragma unroll
            for (int r = 0; r < BITER; r++)
                cpasync16(&BsS[bSm0 + r*B_RSTEP*BLD],
                          bBase + (long)(k0 + r*B_RSTEP)*ldb);
        } else {
            #pragma unroll
            for (int r = 0; r < BITER; r++)
                cpasync16(&BsS[bSm0 + r*B_RSTEP*BLD],
                          bBase + (long)r*B_RSTEP*ldb + k0);
        }
    };

    float d[MT][NT][4];
    #pragma unroll
    for (int i = 0; i < MT; i++)
        #pragma unroll
        for (int j = 0; j < NT; j++)
            #pragma unroll
            for (int r = 0; r < 4; r++) d[i][j][r] = 0.f;

    const int nk = K / BK;

    issue(0, 0); CP_COMMIT();
    if (nk > 1) issue(1, 1);
    CP_COMMIT();

    for (int i = 0; i < nk; i++) {
        CP_WAIT1();
        __syncthreads();

        const int s = i % 3;
        const float* Ab = AsAll + s*ASZ;
        const float* Bb = BsAll + s*BSZ;

        // ---- preload ALL fragments for this BK tile (deep LDS ILP) -----
        uint32_t a[2][MT][4], b[2][NT][2];
        #pragma unroll
        for (int kk = 0; kk < 2; kk++) {
            const int kc = kk*8;
            #pragma unroll
            for (int mt = 0; mt < MT; mt++) {
                const int r = mw + mt*16 + g;
                float v0 = Ab[ r     *ALD + kc + tq    ];
                float v1 = Ab[(r + 8)*ALD + kc + tq    ];
                float v2 = Ab[ r     *ALD + kc + tq + 4];
                float v3 = Ab[(r + 8)*ALD + kc + tq + 4];
                a[kk][mt][0] = CVTA ? f2tf32(v0) : __float_as_uint(v0);
                a[kk][mt][1] = CVTA ? f2tf32(v1) : __float_as_uint(v1);
                a[kk][mt][2] = CVTA ? f2tf32(v2) : __float_as_uint(v2);
                a[kk][mt][3] = CVTA ? f2tf32(v3) : __float_as_uint(v3);
            }
            #pragma unroll
            for (int nt = 0; nt < NT; nt++) {
                const int c = nw + nt*8 + g;
                float v0, v1;
                if (!TRB) {
                    v0 = Bb[(kc + tq    )*BLD + c];
                    v1 = Bb[(kc + tq + 4)*BLD + c];
                } else {
                    v0 = Bb[c*BLD + kc + tq    ];
                    v1 = Bb[c*BLD + kc + tq + 4];
                }
                b[kk][nt][0] = CVTB ? f2tf32(v0) : __float_as_uint(v0);
                b[kk][nt][1] = CVTB ? f2tf32(v1) : __float_as_uint(v1);
            }
        }
        #pragma unroll
        for (int kk = 0; kk < 2; kk++)
            #pragma unroll
            for (int mt = 0; mt < MT; mt++)
                #pragma unroll
                for (int nt = 0; nt < NT; nt++)
                    mma_tf32(d[mt][nt], a[kk][mt], b[kk][nt]);

        if (i + 2 < nk) issue(i + 2, (i + 2) % 3);
        CP_COMMIT();
    }

    // ---- epilogue ------------------------------------------------------
    #pragma unroll
    for (int mt = 0; mt < MT; mt++) {
        const int r0 = row0 + mw + mt*16 + g;
        #pragma unroll
        for (int nt = 0; nt < NT; nt++) {
            const int c = col0 + nw + nt*8 + tq*2;
            float bx = 0.f, by = 0.f;
            if (bias) { bx = bias[c]; by = bias[c+1]; }
            float e0 = alpha*d[mt][nt][0] + bx;
            float e1 = alpha*d[mt][nt][1] + by;
            float e2 = alpha*d[mt][nt][2] + bx;
            float e3 = alpha*d[mt][nt][3] + by;
            if (ROUND) { e0 = roundtf(e0); e1 = roundtf(e1);
                         e2 = roundtf(e2); e3 = roundtf(e3); }
            float2 v0 = { e0, e1 };
            float2 v1 = { e2, e3 };
            *reinterpret_cast<float2*>(&C[(long)r0*ldc + c])     = v0;
            *reinterpret_cast<float2*>(&C[(long)(r0+8)*ldc + c]) = v1;
        }
    }
}

// ---------------------------------------------------------------------------
// Fused softmax + cross-head remix + LayerNorm. One block per (b,i).
// Output rounded to tf32 (consumed by tf32 MMA without per-load cvt).
// ---------------------------------------------------------------------------
__global__ __launch_bounds__(256)
void softmax_remix_ln_kernel(const float* __restrict__ attnA,
                             float*       __restrict__ attnB,
                             const float* __restrict__ W,
                             const float* __restrict__ gamma,
                             const float* __restrict__ beta)
{
    const int i = blockIdx.x;
    const int b = blockIdx.y;
    const int t = threadIdx.x;

    __shared__ float sW[HEADS_*HEADS_];
    __shared__ float sG[HEADS_], sBt[HEADS_];
    __shared__ float red[8][HEADS_];

    if (t < HEADS_*HEADS_) sW[t] = W[t];
    if (t < HEADS_) { sG[t] = gamma[t]; sBt[t] = beta[t]; }

    const long rowbase = (long)b * HEADS_ * NN + (long)i * SEQ_;

    float4 v[HEADS_];
    #pragma unroll
    for (int h = 0; h < HEADS_; h++)
        v[h] = *reinterpret_cast<const float4*>(attnA + rowbase + (long)h*NN + t*4);

    #pragma unroll
    for (int h = 0; h < HEADS_; h++) {
        float m = fmaxf(fmaxf(v[h].x, v[h].y), fmaxf(v[h].z, v[h].w));
        #pragma unroll
        for (int o = 16; o > 0; o >>= 1)
            m = fmaxf(m, __shfl_xor_sync(0xffffffffu, m, o));
        if ((t & 31) == 0) red[t >> 5][h] = m;
    }
    __syncthreads();
    float gm[HEADS_];
    #pragma unroll
    for (int h = 0; h < HEADS_; h++) {
        float m = red[0][h];
        #pragma unroll
        for (int w = 1; w < 8; w++) m = fmaxf(m, red[w][h]);
        gm[h] = m;
    }
    __syncthreads();

    #pragma unroll
    for (int h = 0; h < HEADS_; h++) {
        v[h].x = __expf(v[h].x - gm[h]);
        v[h].y = __expf(v[h].y - gm[h]);
        v[h].z = __expf(v[h].z - gm[h]);
        v[h].w = __expf(v[h].w - gm[h]);
        float s = v[h].x + v[h].y + v[h].z + v[h].w;
        #pragma unroll
        for (int o = 16; o > 0; o >>= 1)
            s += __shfl_xor_sync(0xffffffffu, s, o);
        if ((t & 31) == 0) red[t >> 5][h] = s;
    }
    __syncthreads();
    float inv[HEADS_];
    #pragma unroll
    for (int h = 0; h < HEADS_; h++) {
        float s = red[0][h];
        #pragma unroll
        for (int w = 1; w < 8; w++) s += red[w][h];
        inv[h] = 1.f / s;
    }

    float4 outv[HEADS_];
    #pragma unroll
    for (int u = 0; u < 4; u++) {
        float p[HEADS_];
        #pragma unroll
        for (int h = 0; h < HEADS_; h++) {
            float pv = (u == 0) ? v[h].x : (u == 1) ? v[h].y
                     : (u == 2) ? v[h].z : v[h].w;
            p[h] = pv * inv[h];
        }
        float mixed[HEADS_];
        float mu = 0.f;
        #pragma unroll
        for (int k = 0; k < HEADS_; k++) {
            float s = 0.f;
            #pragma unroll
            for (int h = 0; h < HEADS_; h++) s += p[h] * sW[h*HEADS_ + k];
            mixed[k] = s;
            mu += s;
        }
        mu *= (1.f / HEADS_);
        float var = 0.f;
        #pragma unroll
        for (int k = 0; k < HEADS_; k++) {
            const float dd = mixed[k] - mu;
            var += dd * dd;
        }
        var *= (1.f / HEADS_);
        const float ninv = rsqrtf(var + EPS_);

        #pragma unroll
        for (int k = 0; k < HEADS_; k++) {
            float r = roundtf((mixed[k] - mu) * ninv * sG[k] + sBt[k]);
            if      (u == 0) outv[k].x = r;
            else if (u == 1) outv[k].y = r;
            else if (u == 2) outv[k].z = r;
            else             outv[k].w = r;
        }
    }
    #pragma unroll
    for (int k = 0; k < HEADS_; k++)
        *reinterpret_cast<float4*>(attnB + rowbase + (long)k*NN + t*4) = outv[k];
}

// ---------------------------------------------------------------------------
// Host launcher
// ---------------------------------------------------------------------------
extern "C" void kernel_launch(void* const* d_in, const int* in_sizes, int n_in,
                              void* d_out, int out_size)
{
    const float* x       = (const float*)d_in[0];
    const float* w_qkv   = (const float*)d_in[1];
    const float* reattnW = (const float*)d_in[2];
    const float* gamma   = (const float*)d_in[3];
    const float* beta    = (const float*)d_in[4];
    const float* w_out   = (const float*)d_in[5];
    const float* b_out   = (const float*)d_in[6];
    float* out = (float*)d_out;

    float *qkv, *attnA, *attnB, *outh;
    cudaGetSymbolAddress((void**)&qkv,   g_qkv);
    cudaGetSymbolAddress((void**)&attnA, g_attnA);
    cudaGetSymbolAddress((void**)&attnB, g_attnB);
    cudaGetSymbolAddress((void**)&outh,  g_outh);

    const float scale = 0.125f;

    // smem sizes: 3 * (BM*(BK+4) + BROW*BLD) floats
    constexpr int SM_128x128_N  = 3 * (128*20 + 16*136) * 4;  // 56,832 B
    constexpr int SM_128x128_T  = 3 * (128*20 + 128*20) * 4;  // 61,440 B
    constexpr int SM_128x64_N   = 3 * (128*20 + 16*72) * 4;   // 44,544 B

    // 1) qkv = x @ w_qkv  (cvt both, round output -> Q,K,V are tf32)
    {
        auto k = tgemm_kernel<128,128,2,4,false,true,true,true>;
        cudaFuncSetAttribute(k, cudaFuncAttributeMaxDynamicSharedMemorySize, SM_128x128_N);
        dim3 grid(QKVW/128, TOK/128, 1);
        k<<<grid, 256, SM_128x128_N>>>(
            x, w_qkv, qkv, nullptr,
            DIM_, DIM_, QKVW, QKVW,
            0,0, 0,0, 0,0, 1, 1.f);
    }

    // 2) dots = scale * Q K^T per (b,h) (inputs pre-rounded; keep scores fp32)
    {
        auto k = tgemm_kernel<128,128,2,4,true,false,false,false>;
        cudaFuncSetAttribute(k, cudaFuncAttributeMaxDynamicSharedMemorySize, SM_128x128_T);
        dim3 grid(SEQ_/128, SEQ_/128, B_*HEADS_);
        k<<<grid, 256, SM_128x128_T>>>(
            qkv, qkv + INNER_, attnA, nullptr,
            DH_, QKVW, QKVW, SEQ_,
            (long)SEQ_*QKVW, DH_,
            (long)SEQ_*QKVW, DH_,
            (long)HEADS_*NN,  NN,
            HEADS_, scale);
    }

    // 3) softmax + remix + LN -> attnB (tf32-rounded)
    {
        dim3 grid(SEQ_, B_);
        softmax_remix_ln_kernel<<<grid, 256>>>(attnA, attnB, reattnW, gamma, beta);
    }

    // 4) out_heads = attnB @ V per (b,h) (both pre-rounded; round output)
    {
        auto k = tgemm_kernel<128,64,2,4,false,false,false,true>;
        cudaFuncSetAttribute(k, cudaFuncAttributeMaxDynamicSharedMemorySize, SM_128x64_N);
        dim3 grid(1, SEQ_/128, B_*HEADS_);
        k<<<grid, 256, SM_128x64_N>>>(
            attnB, qkv + 2*INNER_, outh, nullptr,
            SEQ_, SEQ_, QKVW, INNER_,
            (long)HEADS_*NN, NN,
            (long)SEQ_*QKVW, DH_,
            (long)SEQ_*INNER_, DH_,
            HEADS_, 1.f);
    }

    // 5) out = out_heads @ w_out + b_out (A pre-rounded, cvt B, fp32 out)
    {
        auto k = tgemm_kernel<128,128,2,4,false,false,true,false>;
        cudaFuncSetAttribute(k, cudaFuncAttributeMaxDynamicSharedMemorySize, SM_128x128_N);
        dim3 grid(INNER_/128, TOK/128, 1);
        k<<<grid, 256, SM_128x128_N>>>(
            outh, w_out, out, b_out,
            INNER_, INNER_, DIM_, DIM_,
            0,0, 0,0, 0,0, 1, 1.f);
    }
}

// round 6
// speedup vs baseline: 3.3207x; 1.0058x over previous
#include <cuda_runtime.h>
#include <cstdint>

#define DIM_    768
#define HEADS_  12
#define DH_     64
#define INNER_  768
#define B_      4
#define SEQ_    1024
#define EPS_    1e-5f

static constexpr int  TOK  = B_ * SEQ_;          // 4096
static constexpr long NN   = (long)SEQ_ * SEQ_;  // 1M
static constexpr int  QKVW = 3 * INNER_;         // 2304

// ---------------------------------------------------------------------------
// Scratch
// ---------------------------------------------------------------------------
__device__ float g_qkv  [(size_t)TOK * QKVW];
__device__ float g_attnA[(size_t)B_ * HEADS_ * SEQ_ * SEQ_];
__device__ float g_attnB[(size_t)B_ * HEADS_ * SEQ_ * SEQ_];
__device__ float g_outh [(size_t)TOK * INNER_];

// ---------------------------------------------------------------------------
// helpers
// ---------------------------------------------------------------------------
__device__ __forceinline__ uint32_t f2tf32(float f) {
    uint32_t u;
    asm("cvt.rna.tf32.f32 %0, %1;" : "=r"(u) : "f"(f));
    return u;
}
__device__ __forceinline__ float roundtf(float f) {
    return __uint_as_float(f2tf32(f));
}

__device__ __forceinline__ void mma_tf32(float (&d)[4],
                                         const uint32_t (&a)[4],
                                         const uint32_t (&b)[2]) {
    asm volatile(
        "mma.sync.aligned.m16n8k8.row.col.f32.tf32.tf32.f32 "
        "{%0,%1,%2,%3}, {%4,%5,%6,%7}, {%8,%9}, {%0,%1,%2,%3};\n"
        : "+f"(d[0]), "+f"(d[1]), "+f"(d[2]), "+f"(d[3])
        : "r"(a[0]), "r"(a[1]), "r"(a[2]), "r"(a[3]),
          "r"(b[0]), "r"(b[1]));
}

__device__ __forceinline__ void cpasync16(float* smem, const float* gmem) {
    uint32_t s = (uint32_t)__cvta_generic_to_shared(smem);
    asm volatile("cp.async.cg.shared.global [%0], [%1], 16;\n"
                 :: "r"(s), "l"(gmem));
}
#define CP_COMMIT() asm volatile("cp.async.commit_group;\n" ::: "memory")
template<int N> __device__ __forceinline__ void cp_wait() {
    asm volatile("cp.async.wait_group %0;\n" :: "n"(N) : "memory");
}

// ---------------------------------------------------------------------------
// tf32 tensor-core GEMM; cp.async pipeline with STAGES buffers.
//   C[m,n] = alpha * sum_k A[m,k]*B(k,n) (+ bias[n])
//   TRB=false: B is [K,N] row-major.  TRB=true: B is [N,K] row-major.
//   CVTA/CVTB: cvt operand to tf32 at fragment load (false => pre-rounded).
//   ROUND: round C to tf32 before store.
// Requires M%BM==0, N%BN==0, K%BK==0, 256 threads.
// STAGES==1 requires K==BK (single-shot).
// ---------------------------------------------------------------------------
template<int BM, int BN, int BK, int STAGES, int WR, int WC,
         bool TRB, bool CVTA, bool CVTB, bool ROUND>
__global__ __launch_bounds__(256)
void tgemm_kernel(const float* __restrict__ A,
                  const float* __restrict__ B,
                  float*       __restrict__ C,
                  const float* __restrict__ bias,
                  int K, int lda, int ldb, int ldc,
                  long aOuter, long aInner,
                  long bOuter, long bInner,
                  long cOuter, long cInner,
                  int innerDiv, float alpha)
{
    constexpr int NTH  = 256;
    constexpr int MT   = BM / (WR*16);
    constexpr int NT   = BN / (WC*8);
    constexpr int ALD  = BK + 4;
    constexpr int BLD  = TRB ? (BK + 4) : (BN + 8);
    constexpr int BROW = TRB ? BN : BK;
    constexpr int ASZ  = BM * ALD;
    constexpr int BSZ  = BROW * BLD;
    constexpr int KST  = BK / 8;

    extern __shared__ float dynsmem[];
    float* AsAll = dynsmem;
    float* BsAll = dynsmem + STAGES*ASZ;

    const int tid  = threadIdx.x;
    const int wid  = tid >> 5;
    const int lane = tid & 31;
    const int wr   = wid / WC;
    const int wc   = wid % WC;
    const int g    = lane >> 2;
    const int tq   = lane & 3;

    const int z  = blockIdx.z;
    const int zo = z / innerDiv;
    const int zi = z % innerDiv;
    A += zo*aOuter + zi*aInner;
    B += zo*bOuter + zi*bInner;
    C += zo*cOuter + zi*cInner;

    const int row0 = blockIdx.y * BM;
    const int col0 = blockIdx.x * BN;
    const int mw   = wr * (MT*16);
    const int nw   = wc * (NT*8);

    // ---- hoisted load addressing ---------------------------------------
    constexpr int A_TPR   = BK/4;            // threads per A row
    constexpr int A_RSTEP = NTH / A_TPR;
    constexpr int AITER   = BM / A_RSTEP;
    const int aRow = tid / A_TPR;
    const int aC4  = (tid % A_TPR) * 4;
    const float* aBase = A + (long)(row0 + aRow)*lda + aC4;
    const int aSm0 = aRow*ALD + aC4;

    constexpr int B_TPR   = TRB ? (BK/4) : (BN/4);
    constexpr int B_RSTEP = NTH / B_TPR;
    constexpr int BITER   = (TRB ? BN : BK) / B_RSTEP;
    int bSm0;
    const float* bBase;
    if (!TRB) {
        const int bKr = tid / B_TPR;
        const int bC4 = (tid % B_TPR) * 4;
        bBase = B + (long)bKr*ldb + col0 + bC4;
        bSm0  = bKr*BLD + bC4;
    } else {
        const int bN  = tid / B_TPR;
        const int bC4 = (tid % B_TPR) * 4;
        bBase = B + (long)(col0 + bN)*ldb + bC4;
        bSm0  = bN*BLD + bC4;
    }

    auto issue = [&](int kt, int s) {
        const int k0 = kt * BK;
        float* AsS = AsAll + s*ASZ;
        float* BsS = BsAll + s*BSZ;
        #pragma unroll
        for (int r = 0; r < AITER; r++)
            cpasync16(&AsS[aSm0 + r*A_RSTEP*ALD],
                      aBase + (long)r*A_RSTEP*lda + k0);
        if (!TRB) {
            #pragma unroll
            for (int r = 0; r < BITER; r++)
                cpasync16(&BsS[bSm0 + r*B_RSTEP*BLD],
                          bBase + (long)(k0 + r*B_RSTEP)*ldb);
        } else {
            #pragma unroll
            for (int r = 0; r < BITER; r++)
                cpasync16(&BsS[bSm0 + r*B_RSTEP*BLD],
                          bBase + (long)r*B_RSTEP*ldb + k0);
        }
    };

    float d[MT][NT][4];
    #pragma unroll
    for (int i = 0; i < MT; i++)
        #pragma unroll
        for (int j = 0; j < NT; j++)
            #pragma unroll
            for (int r = 0; r < 4; r++) d[i][j][r] = 0.f;

    const int nk = K / BK;

    auto compute = [&](int s) {
        const float* Ab = AsAll + s*ASZ;
        const float* Bb = BsAll + s*BSZ;
        #pragma unroll
        for (int kk = 0; kk < KST; kk++) {
            const int kc = kk*8;
            uint32_t a[MT][4], b[NT][2];
            #pragma unroll
            for (int mt = 0; mt < MT; mt++) {
                const int r = mw + mt*16 + g;
                float v0 = Ab[ r     *ALD + kc + tq    ];
                float v1 = Ab[(r + 8)*ALD + kc + tq    ];
                float v2 = Ab[ r     *ALD + kc + tq + 4];
                float v3 = Ab[(r + 8)*ALD + kc + tq + 4];
                a[mt][0] = CVTA ? f2tf32(v0) : __float_as_uint(v0);
                a[mt][1] = CVTA ? f2tf32(v1) : __float_as_uint(v1);
                a[mt][2] = CVTA ? f2tf32(v2) : __float_as_uint(v2);
                a[mt][3] = CVTA ? f2tf32(v3) : __float_as_uint(v3);
            }
            #pragma unroll
            for (int nt = 0; nt < NT; nt++) {
                const int c = nw + nt*8 + g;
                float v0, v1;
                if (!TRB) {
                    v0 = Bb[(kc + tq    )*BLD + c];
                    v1 = Bb[(kc + tq + 4)*BLD + c];
                } else {
                    v0 = Bb[c*BLD + kc + tq    ];
                    v1 = Bb[c*BLD + kc + tq + 4];
                }
                b[nt][0] = CVTB ? f2tf32(v0) : __float_as_uint(v0);
                b[nt][1] = CVTB ? f2tf32(v1) : __float_as_uint(v1);
            }
            #pragma unroll
            for (int mt = 0; mt < MT; mt++)
                #pragma unroll
                for (int nt = 0; nt < NT; nt++)
                    mma_tf32(d[mt][nt], a[mt], b[nt]);
        }
    };

    if (STAGES == 1) {
        issue(0, 0);
        CP_COMMIT();
        cp_wait<0>();
        __syncthreads();
        compute(0);
    } else {
        constexpr int PRE = STAGES - 1;
        #pragma unroll
        for (int s = 0; s < PRE; s++) {
            if (s < nk) issue(s, s);
            CP_COMMIT();
        }
        for (int i = 0; i < nk; i++) {
            cp_wait<STAGES-2>();
            __syncthreads();
            compute(i % STAGES);
            if (i + PRE < nk) issue(i + PRE, (i + PRE) % STAGES);
            CP_COMMIT();
        }
    }

    // ---- epilogue ------------------------------------------------------
    #pragma unroll
    for (int mt = 0; mt < MT; mt++) {
        const int r0 = row0 + mw + mt*16 + g;
        #pragma unroll
        for (int nt = 0; nt < NT; nt++) {
            const int c = col0 + nw + nt*8 + tq*2;
            float bx = 0.f, by = 0.f;
            if (bias) { bx = bias[c]; by = bias[c+1]; }
            float e0 = alpha*d[mt][nt][0] + bx;
            float e1 = alpha*d[mt][nt][1] + by;
            float e2 = alpha*d[mt][nt][2] + bx;
            float e3 = alpha*d[mt][nt][3] + by;
            if (ROUND) { e0 = roundtf(e0); e1 = roundtf(e1);
                         e2 = roundtf(e2); e3 = roundtf(e3); }
            float2 v0 = { e0, e1 };
            float2 v1 = { e2, e3 };
            *reinterpret_cast<float2*>(&C[(long)r0*ldc + c])     = v0;
            *reinterpret_cast<float2*>(&C[(long)(r0+8)*ldc + c]) = v1;
        }
    }
}

// ---------------------------------------------------------------------------
// Fused softmax + cross-head remix + LayerNorm. One block per (b,i).
// Output rounded to tf32.
// ---------------------------------------------------------------------------
__global__ __launch_bounds__(256)
void softmax_remix_ln_kernel(const float* __restrict__ attnA,
                             float*       __restrict__ attnB,
                             const float* __restrict__ W,
                             const float* __restrict__ gamma,
                             const float* __restrict__ beta)
{
    const int i = blockIdx.x;
    const int b = blockIdx.y;
    const int t = threadIdx.x;

    __shared__ float sW[HEADS_*HEADS_];
    __shared__ float sG[HEADS_], sBt[HEADS_];
    __shared__ float red[8][HEADS_];

    if (t < HEADS_*HEADS_) sW[t] = W[t];
    if (t < HEADS_) { sG[t] = gamma[t]; sBt[t] = beta[t]; }

    const long rowbase = (long)b * HEADS_ * NN + (long)i * SEQ_;

    float4 v[HEADS_];
    #pragma unroll
    for (int h = 0; h < HEADS_; h++)
        v[h] = *reinterpret_cast<const float4*>(attnA + rowbase + (long)h*NN + t*4);

    #pragma unroll
    for (int h = 0; h < HEADS_; h++) {
        float m = fmaxf(fmaxf(v[h].x, v[h].y), fmaxf(v[h].z, v[h].w));
        #pragma unroll
        for (int o = 16; o > 0; o >>= 1)
            m = fmaxf(m, __shfl_xor_sync(0xffffffffu, m, o));
        if ((t & 31) == 0) red[t >> 5][h] = m;
    }
    __syncthreads();
    float gm[HEADS_];
    #pragma unroll
    for (int h = 0; h < HEADS_; h++) {
        float m = red[0][h];
        #pragma unroll
        for (int w = 1; w < 8; w++) m = fmaxf(m, red[w][h]);
        gm[h] = m;
    }
    __syncthreads();

    #pragma unroll
    for (int h = 0; h < HEADS_; h++) {
        v[h].x = __expf(v[h].x - gm[h]);
        v[h].y = __expf(v[h].y - gm[h]);
        v[h].z = __expf(v[h].z - gm[h]);
        v[h].w = __expf(v[h].w - gm[h]);
        float s = v[h].x + v[h].y + v[h].z + v[h].w;
        #pragma unroll
        for (int o = 16; o > 0; o >>= 1)
            s += __shfl_xor_sync(0xffffffffu, s, o);
        if ((t & 31) == 0) red[t >> 5][h] = s;
    }
    __syncthreads();
    float inv[HEADS_];
    #pragma unroll
    for (int h = 0; h < HEADS_; h++) {
        float s = red[0][h];
        #pragma unroll
        for (int w = 1; w < 8; w++) s += red[w][h];
        inv[h] = 1.f / s;
    }

    float4 outv[HEADS_];
    #pragma unroll
    for (int u = 0; u < 4; u++) {
        float p[HEADS_];
        #pragma unroll
        for (int h = 0; h < HEADS_; h++) {
            float pv = (u == 0) ? v[h].x : (u == 1) ? v[h].y
                     : (u == 2) ? v[h].z : v[h].w;
            p[h] = pv * inv[h];
        }
        float mixed[HEADS_];
        float mu = 0.f;
        #pragma unroll
        for (int k = 0; k < HEADS_; k++) {
            float s = 0.f;
            #pragma unroll
            for (int h = 0; h < HEADS_; h++) s += p[h] * sW[h*HEADS_ + k];
            mixed[k] = s;
            mu += s;
        }
        mu *= (1.f / HEADS_);
        float var = 0.f;
        #pragma unroll
        for (int k = 0; k < HEADS_; k++) {
            const float dd = mixed[k] - mu;
            var += dd * dd;
        }
        var *= (1.f / HEADS_);
        const float ninv = rsqrtf(var + EPS_);

        #pragma unroll
        for (int k = 0; k < HEADS_; k++) {
            float r = roundtf((mixed[k] - mu) * ninv * sG[k] + sBt[k]);
            if      (u == 0) outv[k].x = r;
            else if (u == 1) outv[k].y = r;
            else if (u == 2) outv[k].z = r;
            else             outv[k].w = r;
        }
    }
    #pragma unroll
    for (int k = 0; k < HEADS_; k++)
        *reinterpret_cast<float4*>(attnB + rowbase + (long)k*NN + t*4) = outv[k];
}

// ---------------------------------------------------------------------------
// Host launcher
// ---------------------------------------------------------------------------
extern "C" void kernel_launch(void* const* d_in, const int* in_sizes, int n_in,
                              void* d_out, int out_size)
{
    const float* x       = (const float*)d_in[0];
    const float* w_qkv   = (const float*)d_in[1];
    const float* reattnW = (const float*)d_in[2];
    const float* gamma   = (const float*)d_in[3];
    const float* beta    = (const float*)d_in[4];
    const float* w_out   = (const float*)d_in[5];
    const float* b_out   = (const float*)d_in[6];
    float* out = (float*)d_out;

    float *qkv, *attnA, *attnB, *outh;
    cudaGetSymbolAddress((void**)&qkv,   g_qkv);
    cudaGetSymbolAddress((void**)&attnA, g_attnA);
    cudaGetSymbolAddress((void**)&attnB, g_attnB);
    cudaGetSymbolAddress((void**)&outh,  g_outh);

    const float scale = 0.125f;

    // smem bytes: STAGES * (BM*(BK+4) + BROW*BLD) * 4
    constexpr int SM_QKV  = 3 * (128*20 + 16*136) * 4;   // 56,832
    constexpr int SM_DOTS = 1 * (128*68 + 128*68) * 4;   // 69,632
    constexpr int SM_AV   = 4 * (64*20  + 16*72 ) * 4;   // 38,912
    constexpr int SM_OUT  = SM_QKV;

    // 1) qkv = x @ w_qkv  (cvt both, round output -> Q,K,V tf32)
    {
        auto k = tgemm_kernel<128,128,16,3,2,4,false,true,true,true>;
        cudaFuncSetAttribute(k, cudaFuncAttributeMaxDynamicSharedMemorySize, SM_QKV);
        dim3 grid(QKVW/128, TOK/128, 1);
        k<<<grid, 256, SM_QKV>>>(
            x, w_qkv, qkv, nullptr,
            DIM_, DIM_, QKVW, QKVW,
            0,0, 0,0, 0,0, 1, 1.f);
    }

    // 2) dots = scale * Q K^T per (b,h): single-shot BK=64 (K==64)
    {
        auto k = tgemm_kernel<128,128,64,1,2,4,true,false,false,false>;
        cudaFuncSetAttribute(k, cudaFuncAttributeMaxDynamicSharedMemorySize, SM_DOTS);
        dim3 grid(SEQ_/128, SEQ_/128, B_*HEADS_);
        k<<<grid, 256, SM_DOTS>>>(
            qkv, qkv + INNER_, attnA, nullptr,
            DH_, QKVW, QKVW, SEQ_,
            (long)SEQ_*QKVW, DH_,
            (long)SEQ_*QKVW, DH_,
            (long)HEADS_*NN,  NN,
            HEADS_, scale);
    }

    // 3) softmax + remix + LN -> attnB (tf32-rounded)
    {
        dim3 grid(SEQ_, B_);
        softmax_remix_ln_kernel<<<grid, 256>>>(attnA, attnB, reattnW, gamma, beta);
    }

    // 4) out_heads = attnB @ V per (b,h): BM=64 for occupancy, 4 stages
    {
        auto k = tgemm_kernel<64,64,16,4,2,4,false,false,false,true>;
        cudaFuncSetAttribute(k, cudaFuncAttributeMaxDynamicSharedMemorySize, SM_AV);
        dim3 grid(1, SEQ_/64, B_*HEADS_);
        k<<<grid, 256, SM_AV>>>(
            attnB, qkv + 2*INNER_, outh, nullptr,
            SEQ_, SEQ_, QKVW, INNER_,
            (long)HEADS_*NN, NN,
            (long)SEQ_*QKVW, DH_,
            (long)SEQ_*INNER_, DH_,
            HEADS_, 1.f);
    }

    // 5) out = out_heads @ w_out + b_out
    {
        auto k = tgemm_kernel<128,128,16,3,2,4,false,false,true,false>;
        cudaFuncSetAttribute(k, cudaFuncAttributeMaxDynamicSharedMemorySize, SM_OUT);
        dim3 grid(INNER_/128, TOK/128, 1);
        k<<<grid, 256, SM_OUT>>>(
            outh, w_out, out, b_out,
            INNER_, INNER_, DIM_, DIM_,
            0,0, 0,0, 0,0, 1, 1.f);
    }
}